// round 2
// baseline (speedup 1.0000x reference)
#include <cuda_runtime.h>
#include <math.h>

#define N_SAMP  400000
#define XDIMC   128
#define TPB     256
#define S_TILE  128
#define NBLK_A  (N_SAMP / S_TILE)                 /* 3125 exact */
#define NBLK_E  ((N_SAMP + TPB - 1) / TPB)        /* 1563 */
#define NPAY    41
#define DSHIFT  11.313708f

// ---------------- scratch ----------------------------------------------------
__device__ float g_z[3 * N_SAMP];                 // SoA: [z1 | dcos | deuc]
__device__ float g_part1[NBLK_A * NPAY];
__device__ float g_part3[NBLK_E];
__device__ float g_G[256], g_wb[16], g_bb[1];
__device__ float g_loss1[1];
__device__ float g_B[6], g_beta[3], g_alpha[1], g_loss3[1];

// ---------------- f32x2 helpers ----------------------------------------------
#define FMA_F32X2(d, a, b, c) \
    asm("fma.rn.f32x2 %0, %1, %2, %3;" : "=l"(d) : "l"(a), "l"(b), "l"(c))
#define DUP_F32X2(d, x) \
    asm("mov.b64 %0, {%1, %1};" : "=l"(d) : "r"(x))

// ---------------- deterministic block reduction (8 warps) ---------------------
template <int V>
__device__ __forceinline__ void block_reduce8(float (&vals)[V], float* red, float* out) {
    int lane = threadIdx.x & 31;
    int wid  = threadIdx.x >> 5;
#pragma unroll
    for (int v = 0; v < V; v++) {
        float x = vals[v];
#pragma unroll
        for (int o = 16; o > 0; o >>= 1) x += __shfl_down_sync(0xffffffffu, x, o);
        vals[v] = x;
    }
    if (lane == 0) {
#pragma unroll
        for (int v = 0; v < V; v++) red[wid * V + v] = vals[v];
    }
    __syncthreads();
    if ((int)threadIdx.x < V) {
        float s = 0.f;
#pragma unroll
        for (int w = 0; w < 8; w++) s += red[w * V + threadIdx.x];
        out[threadIdx.x] = s;
    }
}

// ---------------- K0: Gram of dec_w3, wb, bb ---------------------------------
__global__ void k_prep(const float* __restrict__ dw3, const float* __restrict__ db3) {
    int tid = threadIdx.x;
    if (tid < 256) {
        int j = tid >> 4, k = tid & 15;
        float s = 0.f;
        for (int i = 0; i < 128; i++) s = fmaf(dw3[j * 128 + i], dw3[k * 128 + i], s);
        g_G[tid] = s;
    }
    if (tid < 16) {
        float s = 0.f;
        for (int i = 0; i < 128; i++) s = fmaf(dw3[tid * 128 + i], db3[i], s);
        g_wb[tid] = s;
    }
    if (tid == 0) {
        float s = 0.f;
        for (int i = 0; i < 128; i++) s = fmaf(db3[i], db3[i], s);
        g_bb[0] = s;
    }
}

// ---------------- dynamic smem layout (floats) -------------------------------
#define SM_X     0                     /* [128][129] = 16512 */
#define SM_W     16512                 /* [128][32]  = 4096  */
#define SM_TR    20608                 /* [128][34]  = 4352  */
#define SM_SMALL 24960
#define SO_B3    (SM_SMALL + 0)        /* 128 */
#define SO_EB1   (SM_SMALL + 128)      /* 16  */
#define SO_EW2   (SM_SMALL + 144)      /* 128 */
#define SO_EB2   (SM_SMALL + 272)      /* 8   */
#define SO_EW3   (SM_SMALL + 280)      /* 8   */
#define SO_EB3   (SM_SMALL + 288)      /* 1   */
#define SO_DW1   (SM_SMALL + 289)      /* 8   */
#define SO_DB1   (SM_SMALL + 297)      /* 8   */
#define SO_DW2   (SM_SMALL + 305)      /* 128 */
#define SO_DB2   (SM_SMALL + 433)      /* 16  */
#define SO_G     (SM_SMALL + 449)      /* 256 */
#define SO_WB    (SM_SMALL + 705)      /* 16  */
#define SO_BB    (SM_SMALL + 721)      /* 1   */
#define SO_TW1   (SM_SMALL + 722)      /* 24  */
#define SO_TB1   (SM_SMALL + 746)      /* 8   */
#define SO_TW2   (SM_SMALL + 754)      /* 32  */
#define SO_TB2   (SM_SMALL + 786)      /* 4   */
#define SO_RED   (SM_SMALL + 790)      /* 4*41 = 164 */
#define SM_FLOATS (SM_SMALL + 954)
#define SM_BYTES  (SM_FLOATS * 4)      /* 103656 */

// ---------------- K1: heavy fused pass ---------------------------------------
__global__ __launch_bounds__(TPB) void k_passA(
    const float* __restrict__ x1,
    const float* __restrict__ ew1, const float* __restrict__ eb1,
    const float* __restrict__ ew2, const float* __restrict__ eb2,
    const float* __restrict__ ew3, const float* __restrict__ eb3,
    const float* __restrict__ dw1, const float* __restrict__ db1,
    const float* __restrict__ dw2, const float* __restrict__ db2,
    const float* __restrict__ dw3, const float* __restrict__ db3,
    const float* __restrict__ tw1, const float* __restrict__ tb1,
    const float* __restrict__ tw2, const float* __restrict__ tb2)
{
    extern __shared__ float sm[];
    float* s_x  = sm + SM_X;
    float* s_w  = sm + SM_W;
    float* s_tr = sm + SM_TR;

    const int tid  = threadIdx.x;
    const int lane = tid & 31;
    const int warp = tid >> 5;

    // ---- load x tile [128 samples][128 k] -> s_x[row*129 + k] (coalesced LDG.128)
    {
        const size_t base = (size_t)blockIdx.x * S_TILE;
#pragma unroll
        for (int r = 0; r < 16; r++) {
            int row = warp * 16 + r;
            float4 v = *reinterpret_cast<const float4*>(x1 + (base + row) * XDIMC + lane * 4);
            float* dst = s_x + row * 129 + lane * 4;
            dst[0] = v.x; dst[1] = v.y; dst[2] = v.z; dst[3] = v.w;
        }
    }
    // ---- combined weight tile s_w[k][0..15]=ew1, s_w[k][16..31]=dw3^T
    for (int idx = tid; idx < 2048; idx += TPB) {
        int k = idx >> 4, j = idx & 15;
        s_w[k * 32 + j] = ew1[idx];
    }
    for (int idx = tid; idx < 2048; idx += TPB) {
        int j = idx >> 7, k = idx & 127;
        s_w[k * 32 + 16 + j] = dw3[idx];
    }
    // ---- small params
    if (tid < 128) sm[SO_B3 + tid]  = db3[tid];
    if (tid < 16)  sm[SO_EB1 + tid] = eb1[tid];
    if (tid < 128) sm[SO_EW2 + tid] = ew2[tid];
    if (tid < 8)   sm[SO_EB2 + tid] = eb2[tid];
    if (tid < 8)   sm[SO_EW3 + tid] = ew3[tid];
    if (tid == 0)  sm[SO_EB3]       = eb3[0];
    if (tid < 8)   sm[SO_DW1 + tid] = dw1[tid];
    if (tid < 8)   sm[SO_DB1 + tid] = db1[tid];
    if (tid < 128) sm[SO_DW2 + tid] = dw2[tid];
    if (tid < 16)  sm[SO_DB2 + tid] = db2[tid];
    {   // Gram (second 256-chunk loader)
        sm[SO_G + tid] = g_G[tid];
    }
    if (tid < 16)  sm[SO_WB + tid]  = g_wb[tid];
    if (tid == 0)  sm[SO_BB]        = g_bb[0];
    if (tid < 24)  sm[SO_TW1 + tid] = tw1[tid];
    if (tid < 8)   sm[SO_TB1 + tid] = tb1[tid];
    if (tid < 32)  sm[SO_TW2 + tid] = tw2[tid];
    if (tid < 4)   sm[SO_TB2 + tid] = tb2[tid];
    __syncthreads();

    // ---- GEMM phase: thread = (tx outputs-group, ty samples-group)
    {
        const int tx = tid & 7;          // 8 output groups of 4
        const int ty = tid >> 3;         // 32 sample groups of 4
        const int o0 = tx * 4;
        const int sb = ty * 4;

        unsigned long long acc[4][2];
#pragma unroll
        for (int j = 0; j < 4; j++) { acc[j][0] = 0ull; acc[j][1] = 0ull; }

        const float* xr0 = s_x + (sb + 0) * 129;
        const float* xr1 = s_x + (sb + 1) * 129;
        const float* xr2 = s_x + (sb + 2) * 129;
        const float* xr3 = s_x + (sb + 3) * 129;
        const float* pw  = s_w + o0;

#pragma unroll 8
        for (int k = 0; k < 128; k++) {
            unsigned long long w0 = *reinterpret_cast<const unsigned long long*>(pw + k * 32);
            unsigned long long w1 = *reinterpret_cast<const unsigned long long*>(pw + k * 32 + 2);
            unsigned long long xd0, xd1, xd2, xd3;
            DUP_F32X2(xd0, __float_as_uint(xr0[k]));
            DUP_F32X2(xd1, __float_as_uint(xr1[k]));
            DUP_F32X2(xd2, __float_as_uint(xr2[k]));
            DUP_F32X2(xd3, __float_as_uint(xr3[k]));
            FMA_F32X2(acc[0][0], xd0, w0, acc[0][0]);
            FMA_F32X2(acc[0][1], xd0, w1, acc[0][1]);
            FMA_F32X2(acc[1][0], xd1, w0, acc[1][0]);
            FMA_F32X2(acc[1][1], xd1, w1, acc[1][1]);
            FMA_F32X2(acc[2][0], xd2, w0, acc[2][0]);
            FMA_F32X2(acc[2][1], xd2, w1, acc[2][1]);
            FMA_F32X2(acc[3][0], xd3, w0, acc[3][0]);
            FMA_F32X2(acc[3][1], xd3, w1, acc[3][1]);
        }
        // write [sample][34] transpose buffer
#pragma unroll
        for (int j = 0; j < 4; j++) {
            unsigned long long* tp =
                reinterpret_cast<unsigned long long*>(s_tr + (sb + j) * 34 + o0);
            tp[0] = acc[j][0];
            tp[1] = acc[j][1];
        }
    }
    __syncthreads();

    // ---- tail: one thread per sample (tid < 128)
    float r[NPAY];
#pragma unroll
    for (int v = 0; v < NPAY; v++) r[v] = 0.f;

    if (tid < S_TILE) {
        const int sloc = tid;
        const int n = blockIdx.x * S_TILE + sloc;

        float u[16], vv[16];
#pragma unroll
        for (int j = 0; j < 16; j++) {
            u[j]  = s_tr[sloc * 34 + j];
            vv[j] = s_tr[sloc * 34 + 16 + j];
        }
        // s = x.x, t = x.b3
        float s = 0.f, t = 0.f;
        const float* xr = s_x + sloc * 129;
#pragma unroll 8
        for (int k = 0; k < 128; k++) {
            float xv = xr[k];
            s = fmaf(xv, xv, s);
            t = fmaf(xv, sm[SO_B3 + k], t);
        }

        // encoder tail
        float a[16];
#pragma unroll
        for (int j = 0; j < 16; j++) a[j] = tanhf(u[j] + sm[SO_EB1 + j]);
        float h2[8];
#pragma unroll
        for (int k = 0; k < 8; k++) {
            float acc = sm[SO_EB2 + k];
#pragma unroll
            for (int j = 0; j < 16; j++) acc = fmaf(a[j], sm[SO_EW2 + j * 8 + k], acc);
            h2[k] = tanhf(acc);
        }
        float z1a = sm[SO_EB3];
#pragma unroll
        for (int k = 0; k < 8; k++) z1a = fmaf(h2[k], sm[SO_EW3 + k], z1a);
        float z1 = tanhf(z1a);

        // decoder to d2[16]
        float d1[8];
#pragma unroll
        for (int k = 0; k < 8; k++) d1[k] = tanhf(fmaf(z1, sm[SO_DW1 + k], sm[SO_DB1 + k]));
        float d2[16];
#pragma unroll
        for (int j = 0; j < 16; j++) {
            float acc = sm[SO_DB2 + j];
#pragma unroll
            for (int k = 0; k < 8; k++) acc = fmaf(d1[k], sm[SO_DW2 + k * 16 + j], acc);
            d2[j] = tanhf(acc);
        }

        // distances via Gram trick
        float hv = 0.f, hwb = 0.f, hGh = 0.f;
#pragma unroll
        for (int j = 0; j < 16; j++) {
            hv  = fmaf(d2[j], vv[j], hv);
            hwb = fmaf(d2[j], sm[SO_WB + j], hwb);
            float gj = 0.f;
#pragma unroll
            for (int k = 0; k < 16; k++) gj = fmaf(sm[SO_G + j * 16 + k], d2[k], gj);
            hGh = fmaf(d2[j], gj, hGh);
        }
        float x1x2  = hv + t;
        float n2    = hGh + 2.f * hwb + sm[SO_BB];
        float eucsq = s - 2.f * x1x2 + n2;
        float deuc  = sqrtf(fmaxf(eucsq, 0.f));
        float dcos  = x1x2 / sqrtf(s * n2);

        // estimator -> softmax
        float e1[8];
#pragma unroll
        for (int k = 0; k < 8; k++) {
            float acc = sm[SO_TB1 + k];
            acc = fmaf(z1,   sm[SO_TW1 + k],      acc);
            acc = fmaf(dcos, sm[SO_TW1 + 8 + k],  acc);
            acc = fmaf(deuc, sm[SO_TW1 + 16 + k], acc);
            e1[k] = tanhf(acc);
        }
        float lg[4];
#pragma unroll
        for (int q = 0; q < 4; q++) {
            float acc = sm[SO_TB2 + q];
#pragma unroll
            for (int k = 0; k < 8; k++) acc = fmaf(e1[k], sm[SO_TW2 + k * 4 + q], acc);
            lg[q] = acc;
        }
        float m = fmaxf(fmaxf(lg[0], lg[1]), fmaxf(lg[2], lg[3]));
        float ex0 = expf(lg[0] - m), ex1 = expf(lg[1] - m);
        float ex2 = expf(lg[2] - m), ex3 = expf(lg[3] - m);
        float inv = 1.f / (ex0 + ex1 + ex2 + ex3);
        float gam[4] = { ex0 * inv, ex1 * inv, ex2 * inv, ex3 * inv };

        // outputs (SoA, coalesced)
        g_z[n]              = z1;
        g_z[N_SAMP + n]     = dcos;
        g_z[2 * N_SAMP + n] = deuc;

        // reduction payload (shifted moments)
        float zc0 = z1, zc1 = dcos, zc2 = deuc - DSHIFT;
        float zz[6] = { zc0 * zc0, zc0 * zc1, zc0 * zc2,
                        zc1 * zc1, zc1 * zc2, zc2 * zc2 };
#pragma unroll
        for (int q = 0; q < 4; q++) {
            r[q] = gam[q];
            r[4 + q * 3 + 0] = gam[q] * zc0;
            r[4 + q * 3 + 1] = gam[q] * zc1;
            r[4 + q * 3 + 2] = gam[q] * zc2;
#pragma unroll
            for (int mmi = 0; mmi < 6; mmi++)
                r[17 + q * 6 + mmi] = gam[q] * zz[mmi];
        }
        r[16] = eucsq;

        // warp reduce (warps 0-3 fully active)
#pragma unroll
        for (int v = 0; v < NPAY; v++) {
            float x = r[v];
#pragma unroll
            for (int o = 16; o > 0; o >>= 1) x += __shfl_down_sync(0xffffffffu, x, o);
            r[v] = x;
        }
        if (lane == 0) {
#pragma unroll
            for (int v = 0; v < NPAY; v++) sm[SO_RED + warp * NPAY + v] = r[v];
        }
    }
    __syncthreads();
    if (tid < NPAY) {
        float ssum = sm[SO_RED + tid] + sm[SO_RED + NPAY + tid]
                   + sm[SO_RED + 2 * NPAY + tid] + sm[SO_RED + 3 * NPAY + tid];
        g_part1[blockIdx.x * NPAY + tid] = ssum;
    }
}

// ---------------- K2: reduce all partials -> GMM params ----------------------
__global__ __launch_bounds__(TPB) void k_reduceAll() {
    __shared__ float red[8 * NPAY];
    __shared__ float sfin[NPAY];
    float acc[NPAY];
#pragma unroll
    for (int v = 0; v < NPAY; v++) acc[v] = 0.f;
    for (int b = threadIdx.x; b < NBLK_A; b += TPB) {
#pragma unroll
        for (int v = 0; v < NPAY; v++) acc[v] += g_part1[b * NPAY + v];
    }
    block_reduce8<NPAY>(acc, red, sfin);
    __syncthreads();

    if (threadIdx.x == 0) {
        const float LOG_2PI = 1.8378770664093454f;
        float B0 = 0.f, B1 = 0.f, B2 = 0.f, B3 = 0.f, B4 = 0.f, B5 = 0.f;
        float be0 = 0.f, be1 = 0.f, be2 = 0.f, alpha = 0.f, l3 = 0.f;
        for (int k = 0; k < 4; k++) {
            float gs = sfin[k];
            float m0s = sfin[4 + k * 3 + 0] / gs;
            float m1s = sfin[4 + k * 3 + 1] / gs;
            float m2s = sfin[4 + k * 3 + 2] / gs;
            float a = sfin[17 + k * 6 + 0] / gs - m0s * m0s;
            float b = sfin[17 + k * 6 + 1] / gs - m0s * m1s;
            float c = sfin[17 + k * 6 + 2] / gs - m0s * m2s;
            float d = sfin[17 + k * 6 + 3] / gs - m1s * m1s;
            float e = sfin[17 + k * 6 + 4] / gs - m1s * m2s;
            float f = sfin[17 + k * 6 + 5] / gs - m2s * m2s;
            float m0 = m0s, m1 = m1s, m2 = m2s + DSHIFT;

            float det = a * (d * f - e * e) - b * (b * f - e * c) + c * (b * e - d * c);
            float id  = 1.f / det;
            float A00 = (d * f - e * e) * id, A01 = (c * e - b * f) * id, A02 = (b * e - c * d) * id;
            float A11 = (a * f - c * c) * id, A12 = (b * c - a * e) * id, A22 = (a * d - b * b) * id;
            float phi = gs / (float)N_SAMP;
            float ck  = logf(phi) - 0.5f * (3.f * LOG_2PI + logf(det));
            float Am0 = A00 * m0 + A01 * m1 + A02 * m2;
            float Am1 = A01 * m0 + A11 * m1 + A12 * m2;
            float Am2 = A02 * m0 + A12 * m1 + A22 * m2;
            float mAm = m0 * Am0 + m1 * Am1 + m2 * Am2;
            B0 += 0.5f * A00; B1 += 0.5f * A01; B2 += 0.5f * A02;
            B3 += 0.5f * A11; B4 += 0.5f * A12; B5 += 0.5f * A22;
            be0 -= Am0; be1 -= Am1; be2 -= Am2;
            alpha += -ck + 0.5f * mAm;
            l3 += 1.f / a + 1.f / d + 1.f / f;
        }
        g_B[0] = B0; g_B[1] = B1; g_B[2] = B2; g_B[3] = B3; g_B[4] = B4; g_B[5] = B5;
        g_beta[0] = be0; g_beta[1] = be1; g_beta[2] = be2;
        g_alpha[0] = alpha;
        g_loss3[0] = 0.0001f * l3;
        g_loss1[0] = sfin[16] / (float)N_SAMP;
    }
}

// ---------------- K3: per-sample energy + partial sums -----------------------
__global__ __launch_bounds__(TPB) void k_energy(float* __restrict__ out) {
    __shared__ float red[8];
    int n = blockIdx.x * TPB + threadIdx.x;
    float r = 0.f;
    if (n < N_SAMP) {
        float z0 = g_z[n], zc = g_z[N_SAMP + n], ze = g_z[2 * N_SAMP + n];
        float q = g_B[0] * z0 * z0 + g_B[3] * zc * zc + g_B[5] * ze * ze
                + 2.f * (g_B[1] * z0 * zc + g_B[2] * z0 * ze + g_B[4] * zc * ze);
        float en = g_alpha[0] + g_beta[0] * z0 + g_beta[1] * zc + g_beta[2] * ze + q;
        out[n] = en;
        r = en;
    }
    int lane = threadIdx.x & 31, wid = threadIdx.x >> 5;
#pragma unroll
    for (int o = 16; o > 0; o >>= 1) r += __shfl_down_sync(0xffffffffu, r, o);
    if (lane == 0) red[wid] = r;
    __syncthreads();
    if (threadIdx.x == 0) {
        float s = 0.f;
#pragma unroll
        for (int w = 0; w < 8; w++) s += red[w];
        g_part3[blockIdx.x] = s;
    }
}

// ---------------- K4: finalize loss ------------------------------------------
__global__ __launch_bounds__(TPB) void k_final(float* __restrict__ out, int out_size) {
    __shared__ float red[8];
    __shared__ float sfin[1];
    float acc[1];
    acc[0] = 0.f;
    for (int b = threadIdx.x; b < NBLK_E; b += TPB) acc[0] += g_part3[b];
    block_reduce8<1>(acc, red, sfin);
    __syncthreads();
    if (threadIdx.x == 0 && out_size > N_SAMP) {
        out[N_SAMP] = g_loss1[0] + 0.01f * (sfin[0] / (float)N_SAMP) + g_loss3[0];
    }
}

// ---------------- launch -----------------------------------------------------
extern "C" void kernel_launch(void* const* d_in, const int* in_sizes, int n_in,
                              void* d_out, int out_size) {
    const float* x1  = (const float*)d_in[0];
    const float* ew1 = (const float*)d_in[1];
    const float* eb1 = (const float*)d_in[2];
    const float* ew2 = (const float*)d_in[3];
    const float* eb2 = (const float*)d_in[4];
    const float* ew3 = (const float*)d_in[5];
    const float* eb3 = (const float*)d_in[6];
    const float* dw1 = (const float*)d_in[7];
    const float* db1 = (const float*)d_in[8];
    const float* dw2 = (const float*)d_in[9];
    const float* db2 = (const float*)d_in[10];
    const float* dw3 = (const float*)d_in[11];
    const float* db3 = (const float*)d_in[12];
    const float* tw1 = (const float*)d_in[13];
    const float* tb1 = (const float*)d_in[14];
    const float* tw2 = (const float*)d_in[15];
    const float* tb2 = (const float*)d_in[16];
    float* out = (float*)d_out;

    cudaFuncSetAttribute(k_passA, cudaFuncAttributeMaxDynamicSharedMemorySize, SM_BYTES);

    k_prep<<<1, 256>>>(dw3, db3);
    k_passA<<<NBLK_A, TPB, SM_BYTES>>>(x1, ew1, eb1, ew2, eb2, ew3, eb3,
                                       dw1, db1, dw2, db2, dw3, db3,
                                       tw1, tb1, tw2, tb2);
    k_reduceAll<<<1, TPB>>>();
    k_energy<<<NBLK_E, TPB>>>(out);
    k_final<<<1, TPB>>>(out, out_size);
}